// round 16
// baseline (speedup 1.0000x reference)
#include <cuda_runtime.h>
#include <math.h>

#define EPSF      1e-10f
#define SIGINV    7000.0f
#define HEIGHT    256
#define WIDTH     256
#define MAXF      256
// logf(1e-10f)
#define LOGMIN    -23.025850929940457f
// band where log-miss contribution is non-negligible: sqrt(18/7000) ~= 0.050709
#define BANDEXP   0.0508f
// cull margin (absorbs rsqrt ~1ulp error; band cutoff itself has huge slack)
#define CULLMARG  0.002f
// tile half-extents in NDC (16x8 pixel tile, pixel centers)
#define HXT       (7.5f / 128.0f)
#define HYT       (3.5f / 128.0f)

// XLA-style contraction of a*b - c*d: fuse the FIRST multiply.
__device__ __forceinline__ float fused_det(float a, float b, float c, float d) {
    return __fmaf_rn(a, b, -__fmul_rn(c, d));
}

__device__ __forceinline__ float edge_d2(float rx, float ry,
                                         float ex, float ey, float inv) {
    float tt = __saturatef((rx * ex + ry * ey) * inv);
    float dx = rx - tt * ex;
    float dy = ry - tt * ey;
    return dx * dx + dy * dy;
}

// transform one vertex: EXACT op sequence of the reference pipeline.
// Also returns camera-space coords (q0,q1,q2) for the normal computation.
__device__ __forceinline__ void xform(const float* __restrict__ pts, int i,
                                      const float* __restrict__ rot,
                                      const float* __restrict__ cpos,
                                      const float* __restrict__ cproj,
                                      float& sx, float& sy,
                                      float& qx, float& qy, float& qz) {
    float a0 = __fsub_rn(pts[i * 3 + 0], cpos[0]);
    float a1 = __fsub_rn(pts[i * 3 + 1], cpos[1]);
    float a2 = __fsub_rn(pts[i * 3 + 2], cpos[2]);
    float q0 = __fmaf_rn(a2, rot[2], __fmaf_rn(a1, rot[1], __fmul_rn(a0, rot[0])));
    float q1 = __fmaf_rn(a2, rot[5], __fmaf_rn(a1, rot[4], __fmul_rn(a0, rot[3])));
    float q2 = __fmaf_rn(a2, rot[8], __fmaf_rn(a1, rot[7], __fmul_rn(a0, rot[6])));
    float x3 = __fmul_rn(q0, cproj[0]);
    float y3 = __fmul_rn(q1, cproj[1]);
    float z3 = __fmul_rn(q2, cproj[2]);
    sx = __fdiv_rn(x3, z3);
    sy = __fdiv_rn(y3, z3);
    qx = q0; qy = q1; qz = q2;
}

// ONE fused kernel: block = 16x8 pixel tile (512 blocks), 256 threads =
// 128 px x 2 warp-pure face-chunks. One thread per face does vertex
// transforms + setup in registers (redundant per block but cheap), culls vs
// tile via bbox + edge-line distance with a rectangle support function
// (rsqrtf; conservative with margin), compacts survivors to shared, runs
// the face loop, combines the 2 chunks, shades. Block 0 writes normals.
__global__ void __launch_bounds__(256)
fused_kernel(const float* __restrict__ pts,
             const int*   __restrict__ faces,
             const float* __restrict__ rot,
             const float* __restrict__ cpos,
             const float* __restrict__ cproj,
             const float* __restrict__ uv,
             const int*   __restrict__ ft,
             const float* __restrict__ tex,
             float* __restrict__ out,
             int P, int F, int th, int tw, int normal_off) {
    __shared__ float4 s0[MAXF], s1[MAXF], s2[MAXF];
    __shared__ float  si[MAXF];
    __shared__ int    sidx[MAXF];
    __shared__ int    wbase[9];
    __shared__ float4 r4[2][128];
    __shared__ int    rk[2][128];
    __shared__ int    rc[2][128];

    int t = threadIdx.x;
    int ti = blockIdx.x >> 4;   // tile row 0..31 (8 px tall)
    int tj = blockIdx.x & 15;   // tile col 0..15 (16 px wide)

    // tile pixel-center bounds
    float txlo = ((float)(tj * 16) + 0.5f) * (1.0f / 128.0f) - 1.0f;
    float txhi = ((float)(tj * 16 + 15) + 0.5f) * (1.0f / 128.0f) - 1.0f;
    float tyhi = 1.0f - (((float)(ti * 8) + 0.5f) * (1.0f / 128.0f));
    float tylo = 1.0f - (((float)(ti * 8 + 7) + 0.5f) * (1.0f / 128.0f));
    float pcx = 0.5f * (txlo + txhi);
    float pcy = 0.5f * (tylo + tyhi);

    // ---- per-face setup, one thread per face, all in registers ----
    bool have = t < F;
    float x0=0,y0=0,x1=0,y1=0,x2=0,y2=0,p0z=0,p1z=0,p2z=0,invA=0,sA=1.0f;
    bool keep = false;

    if (have) {
        int i0 = __ldg(&faces[t * 3 + 0]);
        int i1 = __ldg(&faces[t * 3 + 1]);
        int i2 = __ldg(&faces[t * 3 + 2]);
        float q0x,q0y,q1x,q1y,q2x,q2y;
        xform(pts, i0, rot, cpos, cproj, x0, y0, q0x, q0y, p0z);
        xform(pts, i1, rot, cpos, cproj, x1, y1, q1x, q1y, p1z);
        xform(pts, i2, rot, cpos, cproj, x2, y2, q2x, q2y, p2z);

        // cross(p1-p0, p2-p0): nz needed for validity; full normal block 0.
        float d1x = __fsub_rn(q1x, q0x), d1y = __fsub_rn(q1y, q0y), d1z = __fsub_rn(p1z, p0z);
        float d2x = __fsub_rn(q2x, q0x), d2y = __fsub_rn(q2y, q0y), d2z = __fsub_rn(p2z, p0z);
        float nz = fused_det(d1x, d2y, d1y, d2x);

        if (blockIdx.x == 0) {
            float nx = fused_det(d1y, d2z, d1z, d2y);
            float ny = fused_det(d1z, d2x, d1x, d2z);
            float ss = __fmaf_rn(nz, nz, __fmaf_rn(ny, ny, __fmul_rn(nx, nx)));
            float nn = __fsqrt_rn(ss);
            float den = __fadd_rn(nn, EPSF);
            out[normal_off + t * 3 + 0] = __fdiv_rn(nx, den);
            out[normal_off + t * 3 + 1] = __fdiv_rn(ny, den);
            out[normal_off + t * 3 + 2] = __fdiv_rn(nz, den);
        }

        float A = fused_det(__fsub_rn(x1, x0), __fsub_rn(y2, y0),
                            __fsub_rn(x2, x0), __fsub_rn(y1, y0));
        bool aok = fabsf(A) > EPSF;
        invA = aok ? __fdiv_rn(1.0f, A) : 0.0f;
        sA = (A > 0.0f) ? 1.0f : -1.0f;
        bool valid = aok && (nz > 0.0f);

        if (valid) {
            float xlo = fminf(x0, fminf(x1, x2)) - BANDEXP;
            float xhi = fmaxf(x0, fmaxf(x1, x2)) + BANDEXP;
            float ylo = fminf(y0, fminf(y1, y2)) - BANDEXP;
            float yhi = fmaxf(y0, fmaxf(y1, y2)) + BANDEXP;
            bool bok = !(xhi < txlo || xlo > txhi || yhi < tylo || ylo > tyhi);
            if (bok) {
                // outward unit line normals via rsqrt; rectangle support fn.
                // dist(tile, line) >= d_center - (|nx|hx + |ny|hy); point-
                // to-triangle >= max over edges -> conservative cull.
                float e01x = x1 - x0, e01y = y1 - y0;
                float e12x = x2 - x1, e12y = y2 - y1;
                float e20x = x0 - x2, e20y = y0 - y2;
                float r01 = rsqrtf(e01x * e01x + e01y * e01y + EPSF);
                float r12 = rsqrtf(e12x * e12x + e12y * e12y + EPSF);
                float r20 = rsqrtf(e20x * e20x + e20y * e20y + EPSF);
                float n01x = sA * r01 * e01y, n01y = -sA * r01 * e01x;
                float n12x = sA * r12 * e12y, n12y = -sA * r12 * e12x;
                float n20x = sA * r20 * e20y, n20y = -sA * r20 * e20x;
                float d01 = n01x * (pcx - x0) + n01y * (pcy - y0)
                          - (fabsf(n01x) * HXT + fabsf(n01y) * HYT);
                float d12 = n12x * (pcx - x1) + n12y * (pcy - y1)
                          - (fabsf(n12x) * HXT + fabsf(n12y) * HYT);
                float d20 = n20x * (pcx - x2) + n20y * (pcy - y2)
                          - (fabsf(n20x) * HXT + fabsf(n20y) * HYT);
                keep = fmaxf(d01, fmaxf(d12, d20)) <= (BANDEXP + CULLMARG);
            }
        }
    }

    // order-preserving compaction of kept faces into shared survivor arrays
    unsigned m = __ballot_sync(0xffffffffu, keep);
    int lane = t & 31, warp = t >> 5;
    int pre = __popc(m & ((1u << lane) - 1u));
    if (lane == 0) wbase[warp + 1] = __popc(m);
    __syncthreads();
    if (t == 0) {
        wbase[0] = 0;
        #pragma unroll
        for (int w = 0; w < 8; w++) wbase[w + 1] += wbase[w];
    }
    __syncthreads();
    if (keep) {
        int c = wbase[warp] + pre;
        // exact inverse edge-length^2 (same ops as champion -> identical loop)
        float e01x = x1 - x0, e01y = y1 - y0;
        float e12x = x2 - x1, e12y = y2 - y1;
        float e20x = x0 - x2, e20y = y0 - y2;
        float i01 = 1.0f / (e01x * e01x + e01y * e01y + EPSF);
        float i12 = 1.0f / (e12x * e12x + e12y * e12y + EPSF);
        float i20 = 1.0f / (e20x * e20x + e20y * e20y + EPSF);
        s0[c] = make_float4(x0, y0, x1, y1);
        s1[c] = make_float4(x2, y2, p0z, p1z);
        s2[c] = make_float4(p2z, invA, i01, i12);
        si[c] = i20;
        sidx[c] = t;
    }
    __syncthreads();
    int ns = wbase[8];

    // ---- face loop: 128 px x 2 warp-pure chunks ----
    int p = t & 127;            // pixel within tile
    int chunk = t >> 7;         // 0..1; warp-pure (warps 0-3 vs 4-7)
    int row = ti * 8 + (p >> 4);
    int col = tj * 16 + (p & 15);
    float px = ((float)col + 0.5f) * (1.0f / 128.0f) - 1.0f;
    float py = 1.0f - ((float)row + 0.5f) * (1.0f / 128.0f);

    int q = (ns + 1) >> 1;
    int kbeg = chunk * q;
    int kend = min(kbeg + q, ns);

    float prod = 1.0f;          // product of miss probs (== exp of log-sum)
    int   cnt = 0;
    float bz = -1e10f, bw0 = 0.0f, bw1 = 0.0f;
    int bk = -1;

    for (int k = kbeg; k < kend; k++) {
        float4 A4 = s0[k];
        float4 B4 = s1[k];
        float4 C4 = s2[k];
        float r0x = __fsub_rn(px, A4.x), r0y = __fsub_rn(py, A4.y);
        float r1x = __fsub_rn(px, A4.z), r1y = __fsub_rn(py, A4.w);
        float r2x = __fsub_rn(px, B4.x), r2y = __fsub_rn(py, B4.y);
        float invAk = C4.y;
        float w0 = __fmul_rn(fused_det(r1x, r2y, r2x, r1y), invAk);
        float w1 = __fmul_rn(fused_det(r2x, r0y, r0x, r2y), invAk);
        float w2 = __fsub_rn(__fsub_rn(1.0f, w0), w1);
        bool inside = (w0 >= 0.0f) && (w1 >= 0.0f) && (w2 >= 0.0f);

        if (inside) {
            float z = __fmaf_rn(w2, C4.x, __fmaf_rn(w0, B4.z, __fmul_rn(w1, B4.w)));
            if (z > bz) { bz = z; bk = k; bw0 = w0; bw1 = w1; }
            cnt++;
        } else {
            float e01x = r0x - r1x, e01y = r0y - r1y;
            float e12x = r1x - r2x, e12y = r1y - r2y;
            float e20x = r2x - r0x, e20y = r2y - r0y;
            float d2 = edge_d2(r0x, r0y, e01x, e01y, C4.z);
            d2 = fminf(d2, edge_d2(r1x, r1y, e12x, e12y, C4.w));
            d2 = fminf(d2, edge_d2(r2x, r2y, e20x, e20y, si[k]));
            float aa = d2 * SIGINV;
            if (aa < 18.0f) {
                // miss prob factor; contribution for aa>=18 is |1-m|<1.6e-8
                prod *= fmaxf(1.0f - __expf(-aa), 1e-10f);
            }
        }
    }

    r4[chunk][p] = make_float4(prod, bz, bw0, bw1);
    rk[chunk][p] = bk;
    rc[chunk][p] = cnt;
    __syncthreads();

    if (t < 128) {
        float4 R = r4[0][t];
        float4 O = r4[1][t];
        float fprod = R.x * O.x;
        int fcnt = rc[0][t] + rc[1][t];
        float fz = R.y, fw0 = R.z, fw1 = R.w;
        int fk = rk[0][t];
        // ascending chunk order -> strict > keeps first occurrence
        if (O.y > fz) { fz = O.y; fk = rk[1][t]; fw0 = O.z; fw1 = O.w; }

        int prow = ti * 8 + (t >> 4);
        int pcol = tj * 16 + (t & 15);
        int pix = prow * 256 + pcol;

        // improb = 1 - prod * (1e-10)^cnt
        float hitfac = (fcnt > 0) ? expf((float)fcnt * LOGMIN) : 1.0f;
        out[HEIGHT * WIDTH * 3 + pix] = 1.0f - fprod * hitfac;

        // fragment shader
        float c0 = 0.0f, c1 = 0.0f, c2 = 0.0f;
        if (fk >= 0) {
            int bf = sidx[fk];
            int t0 = __ldg(&ft[bf * 3 + 0]);
            int t1 = __ldg(&ft[bf * 3 + 1]);
            int t2 = __ldg(&ft[bf * 3 + 2]);
            float u0 = __ldg(&uv[t0 * 2]), v0 = __ldg(&uv[t0 * 2 + 1]);
            float u1 = __ldg(&uv[t1 * 2]), v1 = __ldg(&uv[t1 * 2 + 1]);
            float u2 = __ldg(&uv[t2 * 2]), v2 = __ldg(&uv[t2 * 2 + 1]);
            float fw2 = __fsub_rn(__fsub_rn(1.0f, fw0), fw1);
            float u = __fmaf_rn(fw2, u2, __fmaf_rn(fw0, u0, __fmul_rn(fw1, u1)));
            float v = __fmaf_rn(fw2, v2, __fmaf_rn(fw0, v0, __fmul_rn(fw1, v1)));
            float mask = __fadd_rn(__fadd_rn(fw0, fw1), fw2);

            float x = u * (float)(tw - 1);
            float y = (1.0f - v) * (float)(th - 1);
            float x0f = fminf(fmaxf(floorf(x), 0.0f), (float)(tw - 1));
            float y0f = fminf(fmaxf(floorf(y), 0.0f), (float)(th - 1));
            int x0i = (int)x0f, y0i = (int)y0f;
            int x1i = min(x0i + 1, tw - 1);
            int y1i = min(y0i + 1, th - 1);
            float wx = fminf(fmaxf(x - x0f, 0.0f), 1.0f);
            float wy = fminf(fmaxf(y - y0f, 0.0f), 1.0f);

            int cs = th * tw;
            int b00 = y0i * tw + x0i, b01 = y0i * tw + x1i;
            int b10 = y1i * tw + x0i, b11 = y1i * tw + x1i;

            float col3[3];
            #pragma unroll
            for (int ch = 0; ch < 3; ch++) {
                const float* tc = tex + ch * cs;
                float v00 = __ldg(tc + b00), v01 = __ldg(tc + b01);
                float v10 = __ldg(tc + b10), v11 = __ldg(tc + b11);
                float cc = (v00 * (1.0f - wx) + v01 * wx) * (1.0f - wy)
                         + (v10 * (1.0f - wx) + v11 * wx) * wy;
                col3[ch] = fminf(fmaxf(cc * mask, 0.0f), 1.0f);
            }
            c0 = col3[0]; c1 = col3[1]; c2 = col3[2];
        }
        out[pix * 3 + 0] = c0;
        out[pix * 3 + 1] = c1;
        out[pix * 3 + 2] = c2;
    }
}

extern "C" void kernel_launch(void* const* d_in, const int* in_sizes, int n_in,
                              void* d_out, int out_size) {
    const float* pts   = (const float*)d_in[0];
    const int*   faces = (const int*)  d_in[1];
    const float* rot   = (const float*)d_in[2];
    const float* cpos  = (const float*)d_in[3];
    const float* cproj = (const float*)d_in[4];
    const float* uv    = (const float*)d_in[5];
    const int*   ft    = (const int*)  d_in[6];
    const float* tex   = (const float*)d_in[7];

    int P = in_sizes[0] / 3;
    int F = in_sizes[1] / 3;
    int texels = in_sizes[7] / 3;
    int tw = (int)(sqrt((double)texels) + 0.5);
    int th = texels / tw;

    float* out = (float*)d_out;
    int normal_off = HEIGHT * WIDTH * 3 + HEIGHT * WIDTH;

    // single fused kernel: 32 rows x 16 cols of 16x8-pixel tiles
    fused_kernel<<<512, 256>>>(pts, faces, rot, cpos, cproj, uv, ft, tex,
                               out, P, F, th, tw, normal_off);
}